// round 1
// baseline (speedup 1.0000x reference)
#include <cuda_runtime.h>
#include <cstdint>

typedef unsigned long long ull;

#define NTHREADS 256
#define BMAX 2048

// ---------------- device scratch (no allocation allowed) ----------------
__device__ __align__(16) float g_pack[128 * 56];   // [pair q][k=0..27][component e]; k=27 holds -0.5*||s||^2
__device__ float g_feat[BMAX * 450];               // SOM features, [b][450]
__device__ float g_W1t[450 * 400];                 // transposed weights [k][o]
__device__ float g_W2t[400 * 200];
__device__ float g_W3t[200 * 100];
__device__ float g_W4t[100 * 10];

// ---------------- f32x2 helpers (Blackwell packed fp32) ----------------
__device__ __forceinline__ ull ffma2(ull a, ull b, ull c) {
    ull d;
    asm("fma.rn.f32x2 %0, %1, %2, %3;" : "=l"(d) : "l"(a), "l"(b), "l"(c));
    return d;
}
__device__ __forceinline__ ull pack2(float lo, float hi) {
    ull r;
    asm("mov.b64 %0, {%1, %2};" : "=l"(r) : "f"(lo), "f"(hi));
    return r;
}
__device__ __forceinline__ float lo32(ull v) { return __uint_as_float((unsigned)v); }
__device__ __forceinline__ float hi32(ull v) { return __uint_as_float((unsigned)(v >> 32)); }

// ---------------- prep: pack SOM codebook into paired layout ----------------
// som: [16][16][3][3][3] -> flat [256][27] in (C,kh,kw) order (matches patch order).
// pair q holds codes (2q, 2q+1) interleaved: g_pack[q*56 + k*2 + e], k=27 -> -0.5*norm
__global__ void pack_som_kernel(const float* __restrict__ som) {
    int c = threadIdx.x;
    if (c < 256) {
        int q = c >> 1, e = c & 1;
        float nrm = 0.f;
#pragma unroll
        for (int k = 0; k < 27; k++) {
            float v = som[c * 27 + k];
            nrm += v * v;
            g_pack[q * 56 + k * 2 + e] = v;
        }
        g_pack[q * 56 + 54 + e] = -0.5f * nrm;
    }
}

// ---------------- prep: transpose MLP weights to [k][o] ----------------
__global__ void prep_weights(const float* __restrict__ W1, const float* __restrict__ W2,
                             const float* __restrict__ W3, const float* __restrict__ W4) {
    int i0 = blockIdx.x * blockDim.x + threadIdx.x;
    int stride = gridDim.x * blockDim.x;
    for (int i = i0; i < 450 * 400; i += stride) { int o = i / 450, k = i % 450; g_W1t[k * 400 + o] = W1[i]; }
    for (int i = i0; i < 400 * 200; i += stride) { int o = i / 400, k = i % 400; g_W2t[k * 200 + o] = W2[i]; }
    for (int i = i0; i < 200 * 100; i += stride) { int o = i / 200, k = i % 200; g_W3t[k * 100 + o] = W3[i]; }
    for (int i = i0; i < 100 * 10;  i += stride) { int o = i / 100, k = i % 100; g_W4t[k * 10  + o] = W4[i]; }
}

// ---------------- SOM: distances + argmin + feature map ----------------
// One CTA per image. Each thread owns one of 225 patches (15x15 windows, stride 2).
// score(code) = p.s - 0.5||s||^2 ; winner = argmax (ties -> lowest index, matching
// argmin-first-occurrence). Codes processed 2-at-a-time via fma.rn.f32x2, two
// independent pair-accumulators per iteration for ILP.
__global__ __launch_bounds__(256, 2) void som_kernel(const float* __restrict__ x) {
    __shared__ float simg[3072];          // [3][32][32]
    __shared__ double2 spk[128 * 14];     // paired codebook, 16B-load view

    int b = blockIdx.x;
    const float4* xb = (const float4*)(x + (size_t)b * 3072);
    float4* s4 = (float4*)simg;
    for (int i = threadIdx.x; i < 768; i += NTHREADS) s4[i] = xb[i];
    const double2* gp = (const double2*)g_pack;
    for (int i = threadIdx.x; i < 128 * 14; i += NTHREADS) spk[i] = gp[i];
    __syncthreads();

    int t = threadIdx.x;
    if (t < 225) {
        int pr = t / 15, pc = t % 15;
        const float* base = simg + pr * 64 + pc * 2;  // (2*pr)*32 + 2*pc

        ull pp[27];  // patch value duplicated into both halves
#pragma unroll
        for (int c = 0; c < 3; c++)
#pragma unroll
            for (int i = 0; i < 3; i++)
#pragma unroll
                for (int j = 0; j < 3; j++) {
                    float v = base[c * 1024 + i * 32 + j];
                    pp[c * 9 + i * 3 + j] = pack2(v, v);
                }

        float best = -3.4e38f;
        int bidx = 0;
#pragma unroll 1
        for (int q = 0; q < 128; q += 2) {
            const double2* P0 = spk + q * 14;
            const double2* P1 = P0 + 14;
            double2 t0 = P0[13], t1 = P1[13];            // (pair k=26, pair k=27)
            ull a0 = (ull)__double_as_longlong(t0.y);    // init with -0.5*||s||^2 pair
            ull a1 = (ull)__double_as_longlong(t1.y);
            a0 = ffma2(pp[26], (ull)__double_as_longlong(t0.x), a0);
            a1 = ffma2(pp[26], (ull)__double_as_longlong(t1.x), a1);
#pragma unroll
            for (int j = 0; j < 13; j++) {
                double2 v0 = P0[j];
                double2 v1 = P1[j];
                a0 = ffma2(pp[2 * j],     (ull)__double_as_longlong(v0.x), a0);
                a0 = ffma2(pp[2 * j + 1], (ull)__double_as_longlong(v0.y), a0);
                a1 = ffma2(pp[2 * j],     (ull)__double_as_longlong(v1.x), a1);
                a1 = ffma2(pp[2 * j + 1], (ull)__double_as_longlong(v1.y), a1);
            }
            float s0 = lo32(a0), s1 = hi32(a0), s2 = lo32(a1), s3 = hi32(a1);
            if (s0 > best) { best = s0; bidx = 2 * q; }
            if (s1 > best) { best = s1; bidx = 2 * q + 1; }
            if (s2 > best) { best = s2; bidx = 2 * q + 2; }
            if (s3 > best) { best = s3; bidx = 2 * q + 3; }
        }
        float m = (float)(bidx >> 4) * 0.0625f;   // (win // 16) / 16
        float n = (float)(bidx & 15) * 0.0625f;   // (win %  16) / 16
        float* fb = g_feat + (size_t)b * 450;
        fb[t] = m;
        fb[225 + t] = n;                           // channel layout: [m(225), n(225)]
    }
}

// ---------------- MLP: fused 4 layers, 16 images per CTA ----------------
// Activations kept transposed in smem: s[k*18 + i], i = image (0..15), pairs of
// images packed into 64-bit lanes for f32x2. Row stride 18 keeps 8B alignment
// and avoids heavy bank conflicts on transposed stores.
template <int NIN, int NOUT, bool RELU>
__device__ __forceinline__ void layer(const float* __restrict__ Wt, const float* __restrict__ bias,
                                      const float* sin, float* sout) {
    for (int o = threadIdx.x; o < NOUT; o += NTHREADS) {
        float bv = bias[o];
        ull bp = pack2(bv, bv);
        ull acc[8];
#pragma unroll
        for (int p = 0; p < 8; p++) acc[p] = bp;
        const float* wcol = Wt + o;
#pragma unroll 4
        for (int k = 0; k < NIN; k++) {
            float wv = __ldg(wcol + k * NOUT);
            ull wp = pack2(wv, wv);
            const ull* fp = (const ull*)(sin + k * 18);
#pragma unroll
            for (int p = 0; p < 8; p++) acc[p] = ffma2(fp[p], wp, acc[p]);
        }
#pragma unroll
        for (int p = 0; p < 8; p++) {
            float v0 = lo32(acc[p]), v1 = hi32(acc[p]);
            if (RELU) { v0 = fmaxf(v0, 0.f); v1 = fmaxf(v1, 0.f); }
            sout[o * 18 + 2 * p]     = v0;
            sout[o * 18 + 2 * p + 1] = v1;
        }
    }
    __syncthreads();
}

__global__ __launch_bounds__(256) void mlp_kernel(const float* __restrict__ b1, const float* __restrict__ b2,
                                                  const float* __restrict__ b3, const float* __restrict__ b4,
                                                  float* __restrict__ out) {
    extern __shared__ float sm[];
    float* A  = sm;              // up to 450 rows * 18
    float* Bf = sm + 450 * 18;   // up to 400 rows * 18
    int b0 = blockIdx.x * 16;

    // load feature tile transposed: A[k*18 + i] = feat[b0+i][k]
#pragma unroll
    for (int i = 0; i < 16; i++) {
        const float* src = g_feat + (size_t)(b0 + i) * 450;
        for (int k = threadIdx.x; k < 450; k += NTHREADS) A[k * 18 + i] = src[k];
    }
    __syncthreads();

    layer<450, 400, true>(g_W1t, b1, A, Bf);
    layer<400, 200, true>(g_W2t, b2, Bf, A);
    layer<200, 100, true>(g_W3t, b3, A, Bf);

    // final layer 100 -> 10, write to global
    for (int o = threadIdx.x; o < 10; o += NTHREADS) {
        float bv = b4[o];
        ull bp = pack2(bv, bv);
        ull acc[8];
#pragma unroll
        for (int p = 0; p < 8; p++) acc[p] = bp;
#pragma unroll 4
        for (int k = 0; k < 100; k++) {
            float wv = __ldg(&g_W4t[k * 10 + o]);
            ull wp = pack2(wv, wv);
            const ull* fp = (const ull*)(Bf + k * 18);
#pragma unroll
            for (int p = 0; p < 8; p++) acc[p] = ffma2(fp[p], wp, acc[p]);
        }
#pragma unroll
        for (int p = 0; p < 8; p++) {
            out[(size_t)(b0 + 2 * p) * 10 + o]     = lo32(acc[p]);
            out[(size_t)(b0 + 2 * p + 1) * 10 + o] = hi32(acc[p]);
        }
    }
}

// ---------------- launch ----------------
extern "C" void kernel_launch(void* const* d_in, const int* in_sizes, int n_in,
                              void* d_out, int out_size) {
    const float* x   = (const float*)d_in[0];
    const float* som = (const float*)d_in[1];
    const float* W1  = (const float*)d_in[2];
    const float* b1  = (const float*)d_in[3];
    const float* W2  = (const float*)d_in[4];
    const float* b2  = (const float*)d_in[5];
    const float* W3  = (const float*)d_in[6];
    const float* b3  = (const float*)d_in[7];
    const float* W4  = (const float*)d_in[8];
    const float* b4  = (const float*)d_in[9];
    float* out = (float*)d_out;

    int B = in_sizes[0] / 3072;
    if (B > BMAX) B = BMAX;

    cudaFuncSetAttribute(mlp_kernel, cudaFuncAttributeMaxDynamicSharedMemorySize, 62208);

    pack_som_kernel<<<1, 256>>>(som);
    prep_weights<<<256, 256>>>(W1, W2, W3, W4);
    som_kernel<<<B, 256>>>(x);
    mlp_kernel<<<(B + 15) / 16, 256, (450 + 400) * 18 * 4>>>(b1, b2, b3, b4, out);
}

// round 2
// speedup vs baseline: 1.3029x; 1.3029x over previous
#include <cuda_runtime.h>
#include <cstdint>

typedef unsigned long long ull;

#define NTHREADS 256
#define BMAX 2048

// ---------------- device scratch (no allocation allowed) ----------------
__device__ __align__(16) float g_pack[128 * 56];   // [pair q][k=0..27][component e]; k=27 holds -0.5*||s||^2
__device__ __align__(16) float g_feat[BMAX * 450]; // SOM features, [b][450]
__device__ __align__(16) float g_W1t[450 * 400];   // transposed weights [k][o]
__device__ __align__(16) float g_W2t[400 * 200];
__device__ __align__(16) float g_W3t[200 * 100];
__device__ __align__(16) float g_W4t[100 * 10];

// ---------------- f32x2 helpers (Blackwell packed fp32) ----------------
__device__ __forceinline__ ull ffma2(ull a, ull b, ull c) {
    ull d;
    asm("fma.rn.f32x2 %0, %1, %2, %3;" : "=l"(d) : "l"(a), "l"(b), "l"(c));
    return d;
}
__device__ __forceinline__ ull pack2(float lo, float hi) {
    ull r;
    asm("mov.b64 %0, {%1, %2};" : "=l"(r) : "f"(lo), "f"(hi));
    return r;
}
__device__ __forceinline__ float lo32(ull v) { return __uint_as_float((unsigned)v); }
__device__ __forceinline__ float hi32(ull v) { return __uint_as_float((unsigned)(v >> 32)); }

// cp.async 16B (LDGSTS) helpers
__device__ __forceinline__ void cp_async16(uint32_t saddr, const float* g) {
    asm volatile("cp.async.cg.shared.global [%0], [%1], 16;" :: "r"(saddr), "l"(g));
}
#define CP_COMMIT() asm volatile("cp.async.commit_group;")
#define CP_WAIT0()  asm volatile("cp.async.wait_group 0;")

// ---------------- prep: pack SOM codebook into paired layout ----------------
__global__ void pack_som_kernel(const float* __restrict__ som) {
    int c = threadIdx.x;
    if (c < 256) {
        int q = c >> 1, e = c & 1;
        float nrm = 0.f;
#pragma unroll
        for (int k = 0; k < 27; k++) {
            float v = som[c * 27 + k];
            nrm += v * v;
            g_pack[q * 56 + k * 2 + e] = v;
        }
        g_pack[q * 56 + 54 + e] = -0.5f * nrm;
    }
}

// ---------------- prep: transpose MLP weights to [k][o] ----------------
__global__ void prep_weights(const float* __restrict__ W1, const float* __restrict__ W2,
                             const float* __restrict__ W3, const float* __restrict__ W4) {
    int i0 = blockIdx.x * blockDim.x + threadIdx.x;
    int stride = gridDim.x * blockDim.x;
    for (int i = i0; i < 450 * 400; i += stride) { int o = i / 450, k = i % 450; g_W1t[k * 400 + o] = W1[i]; }
    for (int i = i0; i < 400 * 200; i += stride) { int o = i / 400, k = i % 400; g_W2t[k * 200 + o] = W2[i]; }
    for (int i = i0; i < 200 * 100; i += stride) { int o = i / 200, k = i % 200; g_W3t[k * 100 + o] = W3[i]; }
    for (int i = i0; i < 100 * 10;  i += stride) { int o = i / 100, k = i % 100; g_W4t[k * 10  + o] = W4[i]; }
}

// ---------------- SOM: distances + argmin + feature map ----------------
__global__ __launch_bounds__(256, 2) void som_kernel(const float* __restrict__ x) {
    __shared__ float simg[3072];          // [3][32][32]
    __shared__ double2 spk[128 * 14];     // paired codebook, 16B-load view

    int b = blockIdx.x;
    const float4* xb = (const float4*)(x + (size_t)b * 3072);
    float4* s4 = (float4*)simg;
    for (int i = threadIdx.x; i < 768; i += NTHREADS) s4[i] = xb[i];
    const double2* gp = (const double2*)g_pack;
    for (int i = threadIdx.x; i < 128 * 14; i += NTHREADS) spk[i] = gp[i];
    __syncthreads();

    int t = threadIdx.x;
    if (t < 225) {
        int pr = t / 15, pc = t % 15;
        const float* base = simg + pr * 64 + pc * 2;

        ull pp[27];
#pragma unroll
        for (int c = 0; c < 3; c++)
#pragma unroll
            for (int i = 0; i < 3; i++)
#pragma unroll
                for (int j = 0; j < 3; j++) {
                    float v = base[c * 1024 + i * 32 + j];
                    pp[c * 9 + i * 3 + j] = pack2(v, v);
                }

        float best = -3.4e38f;
        int bidx = 0;
#pragma unroll 1
        for (int q = 0; q < 128; q += 2) {
            const double2* P0 = spk + q * 14;
            const double2* P1 = P0 + 14;
            double2 t0 = P0[13], t1 = P1[13];
            ull a0 = (ull)__double_as_longlong(t0.y);
            ull a1 = (ull)__double_as_longlong(t1.y);
            a0 = ffma2(pp[26], (ull)__double_as_longlong(t0.x), a0);
            a1 = ffma2(pp[26], (ull)__double_as_longlong(t1.x), a1);
#pragma unroll
            for (int j = 0; j < 13; j++) {
                double2 v0 = P0[j];
                double2 v1 = P1[j];
                a0 = ffma2(pp[2 * j],     (ull)__double_as_longlong(v0.x), a0);
                a0 = ffma2(pp[2 * j + 1], (ull)__double_as_longlong(v0.y), a0);
                a1 = ffma2(pp[2 * j],     (ull)__double_as_longlong(v1.x), a1);
                a1 = ffma2(pp[2 * j + 1], (ull)__double_as_longlong(v1.y), a1);
            }
            float s0 = lo32(a0), s1 = hi32(a0), s2 = lo32(a1), s3 = hi32(a1);
            if (s0 > best) { best = s0; bidx = 2 * q; }
            if (s1 > best) { best = s1; bidx = 2 * q + 1; }
            if (s2 > best) { best = s2; bidx = 2 * q + 2; }
            if (s3 > best) { best = s3; bidx = 2 * q + 3; }
        }
        float m = (float)(bidx >> 4) * 0.0625f;
        float n = (float)(bidx & 15) * 0.0625f;
        float* fb = g_feat + (size_t)b * 450;
        fb[t] = m;
        fb[225 + t] = n;
    }
}

// ---------------- MLP: fused 4 layers, 8 images per CTA, 256 CTAs ----------------
// Activations transposed in smem: s[k*10 + i], images packed into 4 ulls per row.
// Weights double-buffered through smem via cp.async, chunked CK rows at a time.
// Thread job = (output-pair po, image-group g); NG groups of GU=4/NG ulls each.
// smem layout (floats): A[450*10] | B[400*10] | wbuf[2 * 7200]
#define SM_A 0
#define SM_B 4500
#define SM_W 8500
#define SM_TOTAL_FLOATS (8500 + 2 * 7200)

template <int NIN, int NOUT, int CK, int NG, bool RELU>
__device__ __forceinline__ void layer(const float* __restrict__ Wt, const float* __restrict__ bias,
                                      const float* sin, float* sout, float* wbuf, uint32_t wbuf_s) {
    constexpr int CE = CK * NOUT;          // floats per chunk
    constexpr int NCH = NIN / CK;          // exact by construction
    constexpr int GU = 4 / NG;             // ulls per image-group
    constexpr int JOBS = (NOUT / 2) * NG;
    int tid = threadIdx.x;

    // stage chunk 0
    for (int i = tid; i < CE / 4; i += NTHREADS)
        cp_async16(wbuf_s + i * 16, Wt + i * 4);
    CP_COMMIT(); CP_WAIT0();
    __syncthreads();

    int po = tid / NG, g = tid % NG;
    bool active = tid < JOBS;
    ull acc[2 * GU];
    if (active) {
        float bv0 = bias[2 * po], bv1 = bias[2 * po + 1];
#pragma unroll
        for (int u = 0; u < GU; u++) { acc[u] = pack2(bv0, bv0); acc[GU + u] = pack2(bv1, bv1); }
    }

#pragma unroll 1
    for (int c = 0; c < NCH; c++) {
        const float* w = wbuf + (c & 1) * CE;
        if (c + 1 < NCH) {
            uint32_t dst = wbuf_s + ((c + 1) & 1) * CE * 4;
            const float* src = Wt + (c + 1) * CE;
            for (int i = tid; i < CE / 4; i += NTHREADS) cp_async16(dst + i * 16, src + i * 4);
            CP_COMMIT();
        }
        if (active) {
#pragma unroll
            for (int kk = 0; kk < CK; kk++) {
                int k = c * CK + kk;
                const ull* ar = (const ull*)(sin + k * 10) + g * GU;
                ull wpair = *(const ull*)(w + kk * NOUT + 2 * po);
                float w0 = lo32(wpair), w1 = hi32(wpair);
                ull wp0 = pack2(w0, w0), wp1 = pack2(w1, w1);
#pragma unroll
                for (int u = 0; u < GU; u++) {
                    ull a = ar[u];
                    acc[u]      = ffma2(a, wp0, acc[u]);
                    acc[GU + u] = ffma2(a, wp1, acc[GU + u]);
                }
            }
        }
        CP_WAIT0();
        __syncthreads();
    }

    if (active) {
#pragma unroll
        for (int e = 0; e < 2; e++)
#pragma unroll
            for (int u = 0; u < GU; u++) {
                ull v = acc[e * GU + u];
                float f0 = lo32(v), f1 = hi32(v);
                if (RELU) { f0 = fmaxf(f0, 0.f); f1 = fmaxf(f1, 0.f); }
                ((ull*)(sout + (2 * po + e) * 10))[g * GU + u] = pack2(f0, f1);
            }
    }
    __syncthreads();
}

__global__ __launch_bounds__(256) void mlp_kernel(const float* __restrict__ b1, const float* __restrict__ b2,
                                                  const float* __restrict__ b3, const float* __restrict__ b4,
                                                  float* __restrict__ out) {
    extern __shared__ float sm[];
    float* A = sm + SM_A;
    float* Bf = sm + SM_B;
    float* wbuf = sm + SM_W;
    uint32_t wbuf_s = (uint32_t)__cvta_generic_to_shared(wbuf);
    int tid = threadIdx.x;
    int b0 = blockIdx.x * 8;

    // load feature tile transposed: A[k*10 + i] = feat[b0+i][k], i<8
    for (int i = tid; i < 8 * 450; i += NTHREADS) {
        int img = i / 450, k = i - img * 450;
        A[k * 10 + img] = g_feat[(size_t)(b0 + img) * 450 + k];
    }
    __syncthreads();

    layer<450, 400, 18, 1, true>(g_W1t, b1, A, Bf, wbuf, wbuf_s);
    layer<400, 200, 20, 2, true>(g_W2t, b2, Bf, A, wbuf, wbuf_s);
    layer<200, 100, 25, 4, true>(g_W3t, b3, A, Bf, wbuf, wbuf_s);

    // final layer 100 -> 10: stage all weights (1000 floats) then compute
    for (int i = tid; i < 250; i += NTHREADS)
        cp_async16(wbuf_s + i * 16, g_W4t + i * 4);
    CP_COMMIT(); CP_WAIT0();
    __syncthreads();

    if (tid < 20) {                         // 5 output-pairs x 4 image-groups
        int po = tid >> 2, g = tid & 3;
        float bv0 = b4[2 * po], bv1 = b4[2 * po + 1];
        ull a0 = pack2(bv0, bv0), a1 = pack2(bv1, bv1);
#pragma unroll 4
        for (int k = 0; k < 100; k++) {
            ull wpair = *(const ull*)(wbuf + k * 10 + 2 * po);
            float w0 = lo32(wpair), w1 = hi32(wpair);
            ull a = ((const ull*)(Bf + k * 10))[g];
            a0 = ffma2(a, pack2(w0, w0), a0);
            a1 = ffma2(a, pack2(w1, w1), a1);
        }
        int i0 = b0 + 2 * g;
        out[(size_t)i0 * 10 + 2 * po]           = lo32(a0);
        out[(size_t)(i0 + 1) * 10 + 2 * po]     = hi32(a0);
        out[(size_t)i0 * 10 + 2 * po + 1]       = lo32(a1);
        out[(size_t)(i0 + 1) * 10 + 2 * po + 1] = hi32(a1);
    }
}

// ---------------- launch ----------------
extern "C" void kernel_launch(void* const* d_in, const int* in_sizes, int n_in,
                              void* d_out, int out_size) {
    const float* x   = (const float*)d_in[0];
    const float* som = (const float*)d_in[1];
    const float* W1  = (const float*)d_in[2];
    const float* b1  = (const float*)d_in[3];
    const float* W2  = (const float*)d_in[4];
    const float* b2  = (const float*)d_in[5];
    const float* W3  = (const float*)d_in[6];
    const float* b3  = (const float*)d_in[7];
    const float* W4  = (const float*)d_in[8];
    const float* b4  = (const float*)d_in[9];
    float* out = (float*)d_out;

    int B = in_sizes[0] / 3072;
    if (B > BMAX) B = BMAX;

    static int smem_set = 0;
    cudaFuncSetAttribute(mlp_kernel, cudaFuncAttributeMaxDynamicSharedMemorySize,
                         SM_TOTAL_FLOATS * 4);
    (void)smem_set;

    pack_som_kernel<<<1, 256>>>(som);
    prep_weights<<<256, 256>>>(W1, W2, W3, W4);
    som_kernel<<<B, 256>>>(x);
    mlp_kernel<<<(B + 7) / 8, 256, SM_TOTAL_FLOATS * 4>>>(b1, b2, b3, b4, out);
}

// round 3
// speedup vs baseline: 1.4209x; 1.0906x over previous
#include <cuda_runtime.h>
#include <cstdint>

typedef unsigned long long ull;

#define NTHREADS 256
#define BMAX 2048

// ---------------- device scratch (no allocation allowed) ----------------
__device__ __align__(16) float g_pack[128 * 56];     // paired SOM codebook (+ -0.5*||s||^2)
__device__ __align__(16) float g_feat[BMAX * 450];   // SOM features [b][450]
// weights interleaved [k/4][o][4] (k padded to mult of 4 with zeros)
__device__ __align__(16) float g_W1t[113 * 400 * 4]; // k: 450->452
__device__ __align__(16) float g_W2t[100 * 200 * 4];
__device__ __align__(16) float g_W3t[50 * 100 * 4];
__device__ __align__(16) float g_W4t[25 * 10 * 4];

// ---------------- f32x2 helpers ----------------
__device__ __forceinline__ ull ffma2(ull a, ull b, ull c) {
    ull d;
    asm("fma.rn.f32x2 %0, %1, %2, %3;" : "=l"(d) : "l"(a), "l"(b), "l"(c));
    return d;
}
__device__ __forceinline__ ull pack2(float lo, float hi) {
    ull r;
    asm("mov.b64 %0, {%1, %2};" : "=l"(r) : "f"(lo), "f"(hi));
    return r;
}
__device__ __forceinline__ float lo32(ull v) { return __uint_as_float((unsigned)v); }
__device__ __forceinline__ float hi32(ull v) { return __uint_as_float((unsigned)(v >> 32)); }

// ---------------- prep: pack SOM codebook ----------------
__global__ void pack_som_kernel(const float* __restrict__ som) {
    int c = threadIdx.x;
    if (c < 256) {
        int q = c >> 1, e = c & 1;
        float nrm = 0.f;
#pragma unroll
        for (int k = 0; k < 27; k++) {
            float v = som[c * 27 + k];
            nrm += v * v;
            g_pack[q * 56 + k * 2 + e] = v;
        }
        g_pack[q * 56 + 54 + e] = -0.5f * nrm;
    }
}

// ---------------- prep: interleave weights [k/4][o][4] ----------------
__global__ void prep_weights(const float* __restrict__ W1, const float* __restrict__ W2,
                             const float* __restrict__ W3, const float* __restrict__ W4) {
    int i0 = blockIdx.x * blockDim.x + threadIdx.x;
    int stride = gridDim.x * blockDim.x;
    for (int i = i0; i < 113 * 400 * 4; i += stride) {
        int kg = i / 1600, r = i % 1600, o = r >> 2, kr = r & 3, k = kg * 4 + kr;
        g_W1t[i] = (k < 450) ? W1[o * 450 + k] : 0.f;
    }
    for (int i = i0; i < 100 * 200 * 4; i += stride) {
        int kg = i / 800, r = i % 800, o = r >> 2, kr = r & 3;
        g_W2t[i] = W2[o * 400 + kg * 4 + kr];
    }
    for (int i = i0; i < 50 * 100 * 4; i += stride) {
        int kg = i / 400, r = i % 400, o = r >> 2, kr = r & 3;
        g_W3t[i] = W3[o * 200 + kg * 4 + kr];
    }
    for (int i = i0; i < 25 * 10 * 4; i += stride) {
        int kg = i / 40, r = i % 40, o = r >> 2, kr = r & 3;
        g_W4t[i] = W4[o * 100 + kg * 4 + kr];
    }
}

// ---------------- SOM: flat patch mapping, all 256 threads active ----------------
// patch p = blockIdx*256 + tid; img = p/225. CTA spans at most 3 images; all
// loaded into dynamic smem alongside the paired codebook (64KB total).
__global__ __launch_bounds__(256, 2) void som_kernel(const float* __restrict__ x, int B) {
    extern __shared__ float sm[];
    float* simg = sm;                         // 3 * 3072 floats
    double2* spk = (double2*)(sm + 9216);     // 128 * 14 double2

    int p0 = blockIdx.x * 256;
    int i0 = p0 / 225;
#pragma unroll
    for (int s = 0; s < 3; s++) {
        int img = i0 + s; if (img > B - 1) img = B - 1;
        const float4* xb = (const float4*)(x + (size_t)img * 3072);
        float4* d = (float4*)(simg + s * 3072);
        for (int i = threadIdx.x; i < 768; i += NTHREADS) d[i] = xb[i];
    }
    const double2* gp = (const double2*)g_pack;
    for (int i = threadIdx.x; i < 128 * 14; i += NTHREADS) spk[i] = gp[i];
    __syncthreads();

    int p = p0 + threadIdx.x;
    if (p >= B * 225) return;
    int img = p / 225;
    int t = p - img * 225;
    int pr = t / 15, pc = t % 15;
    const float* base = simg + (img - i0) * 3072 + pr * 64 + pc * 2;

    ull pp[27];
#pragma unroll
    for (int c = 0; c < 3; c++)
#pragma unroll
        for (int i = 0; i < 3; i++)
#pragma unroll
            for (int j = 0; j < 3; j++) {
                float v = base[c * 1024 + i * 32 + j];
                pp[c * 9 + i * 3 + j] = pack2(v, v);
            }

    float best = -3.4e38f;
    int bidx = 0;
#pragma unroll 1
    for (int q = 0; q < 128; q += 2) {
        const double2* P0 = spk + q * 14;
        const double2* P1 = P0 + 14;
        double2 t0 = P0[13], t1 = P1[13];
        ull a0 = (ull)__double_as_longlong(t0.y);
        ull a1 = (ull)__double_as_longlong(t1.y);
        a0 = ffma2(pp[26], (ull)__double_as_longlong(t0.x), a0);
        a1 = ffma2(pp[26], (ull)__double_as_longlong(t1.x), a1);
#pragma unroll
        for (int j = 0; j < 13; j++) {
            double2 v0 = P0[j];
            double2 v1 = P1[j];
            a0 = ffma2(pp[2 * j],     (ull)__double_as_longlong(v0.x), a0);
            a0 = ffma2(pp[2 * j + 1], (ull)__double_as_longlong(v0.y), a0);
            a1 = ffma2(pp[2 * j],     (ull)__double_as_longlong(v1.x), a1);
            a1 = ffma2(pp[2 * j + 1], (ull)__double_as_longlong(v1.y), a1);
        }
        float s0 = lo32(a0), s1 = hi32(a0), s2 = lo32(a1), s3 = hi32(a1);
        if (s0 > best) { best = s0; bidx = 2 * q; }
        if (s1 > best) { best = s1; bidx = 2 * q + 1; }
        if (s2 > best) { best = s2; bidx = 2 * q + 2; }
        if (s3 > best) { best = s3; bidx = 2 * q + 3; }
    }
    float m = (float)(bidx >> 4) * 0.0625f;
    float n = (float)(bidx & 15) * 0.0625f;
    float* fb = g_feat + (size_t)img * 450;
    fb[t] = m;
    fb[225 + t] = n;
}

// ---------------- MLP: fused 4 layers, 8 images/CTA, k-paired f32x2 ----------------
// Activations in smem as [k/4][img][4] floats (2 ulls per image per k-group).
// Weights via coalesced LDG.128 from interleaved [k/4][o][4] — no repacking.
// Job = (output o, image subset of IPJ images). Horizontal lo+hi add at the end.
template <int NGK, int NOUT, int IPJ, bool RELU>
__device__ __forceinline__ void layer(const float* __restrict__ Wg, const float* __restrict__ bias,
                                      const float* sin, float* sout) {
    constexpr int NJ = 8 / IPJ;
    constexpr int JOBS = NOUT * NJ;
    const float4* W4p = (const float4*)Wg;
    for (int job = threadIdx.x; job < JOBS; job += NTHREADS) {
        int o = job / NJ, jg = job % NJ;
        const ull* abase = (const ull*)sin + jg * IPJ * 2;
        const float4* wp = W4p + o;
        ull acc[IPJ];
#pragma unroll
        for (int i = 0; i < IPJ; i++) acc[i] = 0;
#pragma unroll 4
        for (int kg = 0; kg < NGK; kg++) {
            float4 wv = __ldg(wp + kg * NOUT);
            ull wlo = pack2(wv.x, wv.y), whi = pack2(wv.z, wv.w);
            const ull* ar = abase + kg * 16;
#pragma unroll
            for (int i = 0; i < IPJ; i++) {
                acc[i] = ffma2(ar[2 * i],     wlo, acc[i]);
                acc[i] = ffma2(ar[2 * i + 1], whi, acc[i]);
            }
        }
        float bv = __ldg(bias + o);
#pragma unroll
        for (int i = 0; i < IPJ; i++) {
            float v = lo32(acc[i]) + hi32(acc[i]) + bv;
            if (RELU) v = fmaxf(v, 0.f);
            int im = jg * IPJ + i;
            sout[(o >> 2) * 32 + im * 4 + (o & 3)] = v;
        }
    }
    __syncthreads();
}

__global__ __launch_bounds__(256) void mlp_kernel(const float* __restrict__ b1, const float* __restrict__ b2,
                                                  const float* __restrict__ b3, const float* __restrict__ b4,
                                                  float* __restrict__ out, int B) {
    __shared__ float A[113 * 32];   // up to 452 k's x 8 imgs
    __shared__ float Bm[100 * 32];  // up to 400 k's x 8 imgs
    int tid = threadIdx.x;
    int b0 = blockIdx.x * 8;

    // load features [k/4][img][4], zero-pad k=450,451
    for (int i = tid; i < 113 * 32; i += NTHREADS) {
        int kg = i >> 5, r = i & 31, im = r >> 2, kr = r & 3;
        int k = kg * 4 + kr;
        int b = b0 + im; if (b > B - 1) b = B - 1;
        A[i] = (k < 450) ? g_feat[(size_t)b * 450 + k] : 0.f;
    }
    __syncthreads();

    layer<113, 400, 8, true>(g_W1t, b1, A, Bm);   // 450->400
    layer<100, 200, 8, true>(g_W2t, b2, Bm, A);   // 400->200
    layer<50, 100, 4, true>(g_W3t, b3, A, Bm);    // 200->100

    // final 100 -> 10, write global
    for (int job = tid; job < 80; job += NTHREADS) {
        int o = job >> 3, im = job & 7;
        const ull* abase = (const ull*)Bm + im * 2;
        ull acc = 0;
#pragma unroll
        for (int kg = 0; kg < 25; kg++) {
            float4 wv = __ldg((const float4*)g_W4t + kg * 10 + o);
            acc = ffma2(abase[kg * 16],     pack2(wv.x, wv.y), acc);
            acc = ffma2(abase[kg * 16 + 1], pack2(wv.z, wv.w), acc);
        }
        int b = b0 + im;
        if (b < B) out[(size_t)b * 10 + o] = lo32(acc) + hi32(acc) + __ldg(b4 + o);
    }
}

// ---------------- launch ----------------
extern "C" void kernel_launch(void* const* d_in, const int* in_sizes, int n_in,
                              void* d_out, int out_size) {
    const float* x   = (const float*)d_in[0];
    const float* som = (const float*)d_in[1];
    const float* W1  = (const float*)d_in[2];
    const float* b1  = (const float*)d_in[3];
    const float* W2  = (const float*)d_in[4];
    const float* b2  = (const float*)d_in[5];
    const float* W3  = (const float*)d_in[6];
    const float* b3  = (const float*)d_in[7];
    const float* W4  = (const float*)d_in[8];
    const float* b4  = (const float*)d_in[9];
    float* out = (float*)d_out;

    int B = in_sizes[0] / 3072;
    if (B > BMAX) B = BMAX;

    cudaFuncSetAttribute(som_kernel, cudaFuncAttributeMaxDynamicSharedMemorySize, 65536);

    pack_som_kernel<<<1, 256>>>(som);
    prep_weights<<<256, 256>>>(W1, W2, W3, W4);
    int total_p = B * 225;
    som_kernel<<<(total_p + 255) / 256, 256, 65536>>>(x, B);
    mlp_kernel<<<(B + 7) / 8, 256>>>(b1, b2, b3, b4, out, B);
}

// round 4
// speedup vs baseline: 1.4446x; 1.0167x over previous
#include <cuda_runtime.h>
#include <cstdint>

typedef unsigned long long ull;

#define BMAX 2048

// ---------------- device scratch ----------------
__device__ __align__(16) float g_pack[128 * 56];      // paired SOM codebook (+ -0.5*||s||^2)
__device__ __align__(16) float g_feat[BMAX * 450];    // SOM features [b][450]
// weights interleaved [k/4][o][4]; L1 k padded 450->480
__device__ __align__(16) float g_W1t[120 * 400 * 4];
__device__ __align__(16) float g_W2t[100 * 200 * 4];
__device__ __align__(16) float g_W3t[50 * 100 * 4];
__device__ __align__(16) float g_W4t[25 * 10 * 4];

// ---------------- f32x2 helpers ----------------
__device__ __forceinline__ ull ffma2(ull a, ull b, ull c) {
    ull d;
    asm("fma.rn.f32x2 %0, %1, %2, %3;" : "=l"(d) : "l"(a), "l"(b), "l"(c));
    return d;
}
__device__ __forceinline__ ull pack2(float lo, float hi) {
    ull r;
    asm("mov.b64 %0, {%1, %2};" : "=l"(r) : "f"(lo), "f"(hi));
    return r;
}
__device__ __forceinline__ float lo32(ull v) { return __uint_as_float((unsigned)v); }
__device__ __forceinline__ float hi32(ull v) { return __uint_as_float((unsigned)(v >> 32)); }

__device__ __forceinline__ void cp_async16(uint32_t saddr, const float* g) {
    asm volatile("cp.async.cg.shared.global [%0], [%1], 16;" :: "r"(saddr), "l"(g));
}
#define CP_COMMIT() asm volatile("cp.async.commit_group;")
#define CP_WAIT0()  asm volatile("cp.async.wait_group 0;")

// ---------------- prep: pack SOM codebook ----------------
__global__ void pack_som_kernel(const float* __restrict__ som) {
    int c = threadIdx.x;
    if (c < 256) {
        int q = c >> 1, e = c & 1;
        float nrm = 0.f;
#pragma unroll
        for (int k = 0; k < 27; k++) {
            float v = som[c * 27 + k];
            nrm += v * v;
            g_pack[q * 56 + k * 2 + e] = v;
        }
        g_pack[q * 56 + 54 + e] = -0.5f * nrm;
    }
}

// ---------------- prep: interleave weights [k/4][o][4] ----------------
__global__ void prep_weights(const float* __restrict__ W1, const float* __restrict__ W2,
                             const float* __restrict__ W3, const float* __restrict__ W4) {
    int i0 = blockIdx.x * blockDim.x + threadIdx.x;
    int stride = gridDim.x * blockDim.x;
    for (int i = i0; i < 120 * 400 * 4; i += stride) {
        int kg = i / 1600, r = i % 1600, o = r >> 2, kr = r & 3, k = kg * 4 + kr;
        g_W1t[i] = (k < 450) ? W1[o * 450 + k] : 0.f;
    }
    for (int i = i0; i < 100 * 200 * 4; i += stride) {
        int kg = i / 800, r = i % 800, o = r >> 2, kr = r & 3;
        g_W2t[i] = W2[o * 400 + kg * 4 + kr];
    }
    for (int i = i0; i < 50 * 100 * 4; i += stride) {
        int kg = i / 400, r = i % 400, o = r >> 2, kr = r & 3;
        g_W3t[i] = W3[o * 200 + kg * 4 + kr];
    }
    for (int i = i0; i < 25 * 10 * 4; i += stride) {
        int kg = i / 40, r = i % 40, o = r >> 2, kr = r & 3;
        g_W4t[i] = W4[o * 100 + kg * 4 + kr];
    }
}

// ---------------- SOM (unchanged from R3 pass) ----------------
__global__ __launch_bounds__(256, 2) void som_kernel(const float* __restrict__ x, int B) {
    extern __shared__ float sm[];
    float* simg = sm;                         // 3 * 3072 floats
    double2* spk = (double2*)(sm + 9216);     // 128 * 14 double2

    int p0 = blockIdx.x * 256;
    int i0 = p0 / 225;
#pragma unroll
    for (int s = 0; s < 3; s++) {
        int img = i0 + s; if (img > B - 1) img = B - 1;
        const float4* xb = (const float4*)(x + (size_t)img * 3072);
        float4* d = (float4*)(simg + s * 3072);
        for (int i = threadIdx.x; i < 768; i += 256) d[i] = xb[i];
    }
    const double2* gp = (const double2*)g_pack;
    for (int i = threadIdx.x; i < 128 * 14; i += 256) spk[i] = gp[i];
    __syncthreads();

    int p = p0 + threadIdx.x;
    if (p >= B * 225) return;
    int img = p / 225;
    int t = p - img * 225;
    int pr = t / 15, pc = t % 15;
    const float* base = simg + (img - i0) * 3072 + pr * 64 + pc * 2;

    ull pp[27];
#pragma unroll
    for (int c = 0; c < 3; c++)
#pragma unroll
        for (int i = 0; i < 3; i++)
#pragma unroll
            for (int j = 0; j < 3; j++) {
                float v = base[c * 1024 + i * 32 + j];
                pp[c * 9 + i * 3 + j] = pack2(v, v);
            }

    float best = -3.4e38f;
    int bidx = 0;
#pragma unroll 1
    for (int q = 0; q < 128; q += 2) {
        const double2* P0 = spk + q * 14;
        const double2* P1 = P0 + 14;
        double2 t0 = P0[13], t1 = P1[13];
        ull a0 = (ull)__double_as_longlong(t0.y);
        ull a1 = (ull)__double_as_longlong(t1.y);
        a0 = ffma2(pp[26], (ull)__double_as_longlong(t0.x), a0);
        a1 = ffma2(pp[26], (ull)__double_as_longlong(t1.x), a1);
#pragma unroll
        for (int j = 0; j < 13; j++) {
            double2 v0 = P0[j];
            double2 v1 = P1[j];
            a0 = ffma2(pp[2 * j],     (ull)__double_as_longlong(v0.x), a0);
            a0 = ffma2(pp[2 * j + 1], (ull)__double_as_longlong(v0.y), a0);
            a1 = ffma2(pp[2 * j],     (ull)__double_as_longlong(v1.x), a1);
            a1 = ffma2(pp[2 * j + 1], (ull)__double_as_longlong(v1.y), a1);
        }
        float s0 = lo32(a0), s1 = hi32(a0), s2 = lo32(a1), s3 = hi32(a1);
        if (s0 > best) { best = s0; bidx = 2 * q; }
        if (s1 > best) { best = s1; bidx = 2 * q + 1; }
        if (s2 > best) { best = s2; bidx = 2 * q + 2; }
        if (s3 > best) { best = s3; bidx = 2 * q + 3; }
    }
    float m = (float)(bidx >> 4) * 0.0625f;
    float n = (float)(bidx & 15) * 0.0625f;
    float* fb = g_feat + (size_t)img * 450;
    fb[t] = m;
    fb[225 + t] = n;
}

// ---------------- MLP: 512 threads, 16 imgs/CTA, smem-staged weights ----------------
// Activations smem [kg][img][4] (one ulonglong2 per (kg,img)).
// Weights staged to smem in chunks of CK kg-groups, double-buffered cp.async.
// Job = (o, image-group jg of IPJ images). o = job % NOUT -> act loads broadcast
// across lanes, weight LDS.128 coalesced per-lane.
#define MTHREADS 512
#define WBUF_F 12800   // max chunk floats (CK=8 x 400 outs x 4)

// smem float offsets
#define SA 0                      // 120*64 = 7680
#define SB 7680                   // 100*64 = 6400
#define SW 14080                  // 2*12800
#define SM_FLOATS (14080 + 2 * WBUF_F)

template <int NGK, int CK, int NOUT, int IPJ, bool RELU>
__device__ __forceinline__ void layer(const float* __restrict__ Wg, const float* __restrict__ bias,
                                      const float* sin, float* sout, float* wbuf, uint32_t wbuf_s) {
    constexpr int CE = CK * NOUT * 4;     // floats per chunk
    constexpr int NCH = NGK / CK;         // exact
    constexpr int JOBS = NOUT * (16 / IPJ);
    int tid = threadIdx.x;

    // stage chunk 0
    for (int i = tid; i < CE / 4; i += MTHREADS) cp_async16(wbuf_s + i * 16, Wg + i * 4);
    CP_COMMIT(); CP_WAIT0();
    __syncthreads();

    ull acc[(JOBS + MTHREADS - 1) / MTHREADS > 1 ? 2 * IPJ : IPJ];  // per-thread up to 2 jobs
    constexpr int MAXJ = (JOBS + MTHREADS - 1) / MTHREADS;
#pragma unroll
    for (int i = 0; i < (MAXJ > 1 ? 2 * IPJ : IPJ); i++) acc[i] = 0;

#pragma unroll 1
    for (int c = 0; c < NCH; c++) {
        const float* w = wbuf + (c & 1) * WBUF_F;
        if (c + 1 < NCH) {
            uint32_t dst = wbuf_s + ((c + 1) & 1) * WBUF_F * 4;
            const float* src = Wg + (c + 1) * CE;
            for (int i = tid; i < CE / 4; i += MTHREADS) cp_async16(dst + i * 16, src + i * 4);
            CP_COMMIT();
        }
#pragma unroll
        for (int jj = 0; jj < MAXJ; jj++) {
            int job = tid + jj * MTHREADS;
            if (job < JOBS) {
                int o = job % NOUT, jg = job / NOUT;
                const ulonglong2* wrow = (const ulonglong2*)w + o;
                const ulonglong2* arow = (const ulonglong2*)sin + (size_t)c * CK * 16 + jg * IPJ;
#pragma unroll
                for (int kk = 0; kk < CK; kk++) {
                    ulonglong2 wv = wrow[kk * NOUT];
                    const ulonglong2* ar = arow + kk * 16;
#pragma unroll
                    for (int i = 0; i < IPJ; i++) {
                        ulonglong2 av = ar[i];
                        acc[jj * IPJ + i] = ffma2(av.x, wv.x, acc[jj * IPJ + i]);
                        acc[jj * IPJ + i] = ffma2(av.y, wv.y, acc[jj * IPJ + i]);
                    }
                }
            }
        }
        CP_WAIT0();
        __syncthreads();
    }

#pragma unroll
    for (int jj = 0; jj < MAXJ; jj++) {
        int job = tid + jj * MTHREADS;
        if (job < JOBS) {
            int o = job % NOUT, jg = job / NOUT;
            float bv = __ldg(bias + o);
#pragma unroll
            for (int i = 0; i < IPJ; i++) {
                float v = lo32(acc[jj * IPJ + i]) + hi32(acc[jj * IPJ + i]) + bv;
                if (RELU) v = fmaxf(v, 0.f);
                int im = jg * IPJ + i;
                sout[(o >> 2) * 64 + im * 4 + (o & 3)] = v;
            }
        }
    }
    __syncthreads();
}

__global__ __launch_bounds__(MTHREADS) void mlp_kernel(const float* __restrict__ b1, const float* __restrict__ b2,
                                                       const float* __restrict__ b3, const float* __restrict__ b4,
                                                       float* __restrict__ out, int B) {
    extern __shared__ float sm[];
    float* A = sm + SA;
    float* Bm = sm + SB;
    float* wbuf = sm + SW;
    uint32_t wbuf_s = (uint32_t)__cvta_generic_to_shared(wbuf);
    int tid = threadIdx.x;
    int b0 = blockIdx.x * 16;

    // features -> A [kg][img][4], zero-pad k >= 450
    for (int i = tid; i < 120 * 64; i += MTHREADS) {
        int kg = i >> 6, r = i & 63, im = r >> 2, kr = r & 3;
        int k = kg * 4 + kr;
        int b = b0 + im; if (b > B - 1) b = B - 1;
        A[i] = (k < 450) ? g_feat[(size_t)b * 450 + k] : 0.f;
    }
    __syncthreads();

    layer<120, 8, 400, 8, true>(g_W1t, b1, A, Bm, wbuf, wbuf_s);   // 450(480)->400
    layer<100, 10, 200, 4, true>(g_W2t, b2, Bm, A, wbuf, wbuf_s);  // 400->200
    layer<50, 10, 100, 2, true>(g_W3t, b3, A, Bm, wbuf, wbuf_s);   // 200->100

    // final 100 -> 10 (weights tiny: 4KB, L1-resident via __ldg)
    for (int job = tid; job < 160; job += MTHREADS) {
        int o = job % 10, im = job / 10;
        const ulonglong2* ar = (const ulonglong2*)Bm + im;
        ull acc = 0;
#pragma unroll
        for (int kg = 0; kg < 25; kg++) {
            ulonglong2 wv = __ldg((const ulonglong2*)g_W4t + kg * 10 + o);
            ulonglong2 av = ar[kg * 16];
            acc = ffma2(av.x, wv.x, acc);
            acc = ffma2(av.y, wv.y, acc);
        }
        int b = b0 + im;
        if (b < B) out[(size_t)b * 10 + o] = lo32(acc) + hi32(acc) + __ldg(b4 + o);
    }
}

// ---------------- launch ----------------
extern "C" void kernel_launch(void* const* d_in, const int* in_sizes, int n_in,
                              void* d_out, int out_size) {
    const float* x   = (const float*)d_in[0];
    const float* som = (const float*)d_in[1];
    const float* W1  = (const float*)d_in[2];
    const float* b1  = (const float*)d_in[3];
    const float* W2  = (const float*)d_in[4];
    const float* b2  = (const float*)d_in[5];
    const float* W3  = (const float*)d_in[6];
    const float* b3  = (const float*)d_in[7];
    const float* W4  = (const float*)d_in[8];
    const float* b4  = (const float*)d_in[9];
    float* out = (float*)d_out;

    int B = in_sizes[0] / 3072;
    if (B > BMAX) B = BMAX;

    cudaFuncSetAttribute(som_kernel, cudaFuncAttributeMaxDynamicSharedMemorySize, 65536);
    cudaFuncSetAttribute(mlp_kernel, cudaFuncAttributeMaxDynamicSharedMemorySize, SM_FLOATS * 4);

    pack_som_kernel<<<1, 256>>>(som);
    prep_weights<<<256, 256>>>(W1, W2, W3, W4);
    int total_p = B * 225;
    som_kernel<<<(total_p + 255) / 256, 256, 65536>>>(x, B);
    mlp_kernel<<<(B + 15) / 16, MTHREADS, SM_FLOATS * 4>>>(b1, b2, b3, b4, out, B);
}

// round 5
// speedup vs baseline: 1.4936x; 1.0339x over previous
#include <cuda_runtime.h>
#include <cstdint>

typedef unsigned long long ull;

#define BMAX 2048

// ---------------- device scratch ----------------
__device__ __align__(16) float g_pack[128 * 56];      // paired SOM codebook (+ -0.5*||s||^2)
__device__ __align__(16) float g_feat[BMAX * 450];    // SOM features [b][450]
// weights, layer-specific interleave [kg][j][og][4] (OPT=4 for L1, 2 for L2/L3)
__device__ __align__(16) float g_W1t[120 * 400 * 4];  // k padded 450->480
__device__ __align__(16) float g_W2t[100 * 200 * 4];
__device__ __align__(16) float g_W3t[50 * 100 * 4];
__device__ __align__(16) float g_W4t[25 * 10 * 4];    // [kg][o][4]

// ---------------- f32x2 helpers ----------------
__device__ __forceinline__ ull ffma2(ull a, ull b, ull c) {
    ull d;
    asm("fma.rn.f32x2 %0, %1, %2, %3;" : "=l"(d) : "l"(a), "l"(b), "l"(c));
    return d;
}
__device__ __forceinline__ ull pack2(float lo, float hi) {
    ull r;
    asm("mov.b64 %0, {%1, %2};" : "=l"(r) : "f"(lo), "f"(hi));
    return r;
}
__device__ __forceinline__ float lo32(ull v) { return __uint_as_float((unsigned)v); }
__device__ __forceinline__ float hi32(ull v) { return __uint_as_float((unsigned)(v >> 32)); }

__device__ __forceinline__ void cp_async16(uint32_t saddr, const float* g) {
    asm volatile("cp.async.cg.shared.global [%0], [%1], 16;" :: "r"(saddr), "l"(g));
}
#define CP_COMMIT() asm volatile("cp.async.commit_group;")
#define CP_WAIT0()  asm volatile("cp.async.wait_group 0;")

// ---------------- prep: pack SOM codebook ----------------
__global__ void pack_som_kernel(const float* __restrict__ som) {
    int c = threadIdx.x;
    if (c < 256) {
        int q = c >> 1, e = c & 1;
        float nrm = 0.f;
#pragma unroll
        for (int k = 0; k < 27; k++) {
            float v = som[c * 27 + k];
            nrm += v * v;
            g_pack[q * 56 + k * 2 + e] = v;
        }
        g_pack[q * 56 + 54 + e] = -0.5f * nrm;
    }
}

// ---------------- prep: interleave weights [kg][j][og][4] ----------------
__global__ void prep_weights(const float* __restrict__ W1, const float* __restrict__ W2,
                             const float* __restrict__ W3, const float* __restrict__ W4) {
    int i0 = blockIdx.x * blockDim.x + threadIdx.x;
    int stride = gridDim.x * blockDim.x;
    // L1: OPT=4, NOG=100, 120 kg (k padded to 480)
    for (int i = i0; i < 120 * 400 * 4; i += stride) {
        int kr = i & 3, r = i >> 2;
        int og = r % 100; r /= 100;
        int j = r & 3; int kg = r >> 2;
        int k = kg * 4 + kr, o = og * 4 + j;
        g_W1t[i] = (k < 450) ? W1[o * 450 + k] : 0.f;
    }
    // L2: OPT=2, NOG=100, 100 kg
    for (int i = i0; i < 100 * 200 * 4; i += stride) {
        int kr = i & 3, r = i >> 2;
        int og = r % 100; r /= 100;
        int j = r & 1; int kg = r >> 1;
        g_W2t[i] = W2[(og * 2 + j) * 400 + kg * 4 + kr];
    }
    // L3: OPT=2, NOG=50, 50 kg
    for (int i = i0; i < 50 * 100 * 4; i += stride) {
        int kr = i & 3, r = i >> 2;
        int og = r % 50; r /= 50;
        int j = r & 1; int kg = r >> 1;
        g_W3t[i] = W3[(og * 2 + j) * 200 + kg * 4 + kr];
    }
    // L4: [kg][o][4]
    for (int i = i0; i < 25 * 10 * 4; i += stride) {
        int kg = i / 40, r = i % 40, o = r >> 2, kr = r & 3;
        g_W4t[i] = W4[o * 100 + kg * 4 + kr];
    }
}

// ---------------- SOM (unchanged, passing) ----------------
__global__ __launch_bounds__(256, 2) void som_kernel(const float* __restrict__ x, int B) {
    extern __shared__ float sm[];
    float* simg = sm;                         // 3 * 3072 floats
    double2* spk = (double2*)(sm + 9216);     // 128 * 14 double2

    int p0 = blockIdx.x * 256;
    int i0 = p0 / 225;
#pragma unroll
    for (int s = 0; s < 3; s++) {
        int img = i0 + s; if (img > B - 1) img = B - 1;
        const float4* xb = (const float4*)(x + (size_t)img * 3072);
        float4* d = (float4*)(simg + s * 3072);
        for (int i = threadIdx.x; i < 768; i += 256) d[i] = xb[i];
    }
    const double2* gp = (const double2*)g_pack;
    for (int i = threadIdx.x; i < 128 * 14; i += 256) spk[i] = gp[i];
    __syncthreads();

    int p = p0 + threadIdx.x;
    if (p >= B * 225) return;
    int img = p / 225;
    int t = p - img * 225;
    int pr = t / 15, pc = t % 15;
    const float* base = simg + (img - i0) * 3072 + pr * 64 + pc * 2;

    ull pp[27];
#pragma unroll
    for (int c = 0; c < 3; c++)
#pragma unroll
        for (int i = 0; i < 3; i++)
#pragma unroll
            for (int j = 0; j < 3; j++) {
                float v = base[c * 1024 + i * 32 + j];
                pp[c * 9 + i * 3 + j] = pack2(v, v);
            }

    float best = -3.4e38f;
    int bidx = 0;
#pragma unroll 1
    for (int q = 0; q < 128; q += 2) {
        const double2* P0 = spk + q * 14;
        const double2* P1 = P0 + 14;
        double2 t0 = P0[13], t1 = P1[13];
        ull a0 = (ull)__double_as_longlong(t0.y);
        ull a1 = (ull)__double_as_longlong(t1.y);
        a0 = ffma2(pp[26], (ull)__double_as_longlong(t0.x), a0);
        a1 = ffma2(pp[26], (ull)__double_as_longlong(t1.x), a1);
#pragma unroll
        for (int j = 0; j < 13; j++) {
            double2 v0 = P0[j];
            double2 v1 = P1[j];
            a0 = ffma2(pp[2 * j],     (ull)__double_as_longlong(v0.x), a0);
            a0 = ffma2(pp[2 * j + 1], (ull)__double_as_longlong(v0.y), a0);
            a1 = ffma2(pp[2 * j],     (ull)__double_as_longlong(v1.x), a1);
            a1 = ffma2(pp[2 * j + 1], (ull)__double_as_longlong(v1.y), a1);
        }
        float s0 = lo32(a0), s1 = hi32(a0), s2 = lo32(a1), s3 = hi32(a1);
        if (s0 > best) { best = s0; bidx = 2 * q; }
        if (s1 > best) { best = s1; bidx = 2 * q + 1; }
        if (s2 > best) { best = s2; bidx = 2 * q + 2; }
        if (s3 > best) { best = s3; bidx = 2 * q + 3; }
    }
    float m = (float)(bidx >> 4) * 0.0625f;
    float n = (float)(bidx & 15) * 0.0625f;
    float* fb = g_feat + (size_t)img * 450;
    fb[t] = m;
    fb[225 + t] = n;
}

// ---------------- MLP: 8 imgs/CTA, 256 thr, OPTxIMG register tiling ----------------
// Act smem [kg][img] ulonglong2 (4 k-values per img). Weight smem [kg][j][og]
// ulonglong2, double-buffered cp.async chunks of CK kg's.
// Thread job = (og, jg): OPT outputs x IMG images, acc = OPT*IMG f32x2.
#define MTHREADS 256
#define NIMG 8
#define WBUF_U2 2400    // max chunk in ulonglong2 (CK=6 x 400 x 1) = 9600 floats

// smem layout in ulonglong2 units: A[120*8] | B[100*8] | wbuf[2*2400]
#define SA_U2 0
#define SB_U2 960
#define SW_U2 1760
#define SM_U2 (1760 + 2 * WBUF_U2)

template <int NGK, int CK, int NOUT, int OPT, int IMG, bool RELU>
__device__ __forceinline__ void layer(const float* __restrict__ Wg, const float* __restrict__ bias,
                                      const ulonglong2* sin, float* sout,
                                      ulonglong2* wbuf, uint32_t wbuf_s) {
    constexpr int NOG = NOUT / OPT;
    constexpr int NJG = NIMG / IMG;
    constexpr int JOBS = NOG * NJG;          // == 200 for L1..L3
    constexpr int CEF = CK * NOUT * 4;       // floats per chunk
    constexpr int NCH = NGK / CK;            // exact
    int tid = threadIdx.x;

    // stage chunk 0
    for (int i = tid; i < CEF / 4; i += MTHREADS) cp_async16(wbuf_s + i * 16, Wg + i * 4);
    CP_COMMIT(); CP_WAIT0();
    __syncthreads();

    int og = tid % NOG, jg = tid / NOG;
    bool active = tid < JOBS;
    ull acc[OPT * IMG];
#pragma unroll
    for (int i = 0; i < OPT * IMG; i++) acc[i] = 0;

#pragma unroll 1
    for (int c = 0; c < NCH; c++) {
        const ulonglong2* w = wbuf + (c & 1) * WBUF_U2;
        if (c + 1 < NCH) {
            uint32_t dst = wbuf_s + ((c + 1) & 1) * WBUF_U2 * 16;
            const float* src = Wg + (c + 1) * CEF;
            for (int i = tid; i < CEF / 4; i += MTHREADS) cp_async16(dst + i * 16, src + i * 4);
            CP_COMMIT();
        }
        if (active) {
#pragma unroll
            for (int kk = 0; kk < CK; kk++) {
                ulonglong2 av[IMG], wv[OPT];
#pragma unroll
                for (int i = 0; i < IMG; i++)
                    av[i] = sin[(c * CK + kk) * NIMG + jg * IMG + i];
#pragma unroll
                for (int j = 0; j < OPT; j++)
                    wv[j] = w[(kk * OPT + j) * NOG + og];
#pragma unroll
                for (int j = 0; j < OPT; j++)
#pragma unroll
                    for (int i = 0; i < IMG; i++) {
                        acc[j * IMG + i] = ffma2(av[i].x, wv[j].x, acc[j * IMG + i]);
                        acc[j * IMG + i] = ffma2(av[i].y, wv[j].y, acc[j * IMG + i]);
                    }
            }
        }
        CP_WAIT0();
        __syncthreads();
    }

    if (active) {
#pragma unroll
        for (int j = 0; j < OPT; j++) {
            int o = og * OPT + j;
            float bv = __ldg(bias + o);
#pragma unroll
            for (int i = 0; i < IMG; i++) {
                float v = lo32(acc[j * IMG + i]) + hi32(acc[j * IMG + i]) + bv;
                if (RELU) v = fmaxf(v, 0.f);
                int im = jg * IMG + i;
                sout[((o >> 2) * NIMG + im) * 4 + (o & 3)] = v;
            }
        }
    }
    __syncthreads();
}

__global__ __launch_bounds__(MTHREADS, 2) void mlp_kernel(const float* __restrict__ b1, const float* __restrict__ b2,
                                                          const float* __restrict__ b3, const float* __restrict__ b4,
                                                          float* __restrict__ out, int B) {
    extern __shared__ ulonglong2 smu[];
    ulonglong2* A = smu + SA_U2;
    ulonglong2* Bm = smu + SB_U2;
    ulonglong2* wbuf = smu + SW_U2;
    uint32_t wbuf_s = (uint32_t)__cvta_generic_to_shared(wbuf);
    int tid = threadIdx.x;
    int b0 = blockIdx.x * NIMG;

    // features -> A [kg][img][4], zero-pad k >= 450
    float* Af = (float*)A;
    for (int i = tid; i < 120 * NIMG * 4; i += MTHREADS) {
        int kg = i >> 5, r = i & 31, im = r >> 2, kr = r & 3;
        int k = kg * 4 + kr;
        int b = b0 + im; if (b > B - 1) b = B - 1;
        Af[i] = (k < 450) ? g_feat[(size_t)b * 450 + k] : 0.f;
    }
    __syncthreads();

    layer<120, 6, 400, 4, 4, true>(g_W1t, b1, A, (float*)Bm, wbuf, wbuf_s);   // 450(480)->400
    layer<100, 10, 200, 2, 4, true>(g_W2t, b2, Bm, (float*)A, wbuf, wbuf_s);  // 400->200
    layer<50, 10, 100, 2, 2, true>(g_W3t, b3, A, (float*)Bm, wbuf, wbuf_s);   // 200->100

    // final 100 -> 10 (weights tiny; L1-resident __ldg)
    for (int job = tid; job < 10 * NIMG; job += MTHREADS) {
        int o = job % 10, im = job / 10;
        const ulonglong2* ar = Bm + im;
        ull acc = 0;
#pragma unroll
        for (int kg = 0; kg < 25; kg++) {
            ulonglong2 wv = __ldg((const ulonglong2*)g_W4t + kg * 10 + o);
            ulonglong2 av = ar[kg * NIMG];
            acc = ffma2(av.x, wv.x, acc);
            acc = ffma2(av.y, wv.y, acc);
        }
        int b = b0 + im;
        if (b < B) out[(size_t)b * 10 + o] = lo32(acc) + hi32(acc) + __ldg(b4 + o);
    }
}

// ---------------- launch ----------------
extern "C" void kernel_launch(void* const* d_in, const int* in_sizes, int n_in,
                              void* d_out, int out_size) {
    const float* x   = (const float*)d_in[0];
    const float* som = (const float*)d_in[1];
    const float* W1  = (const float*)d_in[2];
    const float* b1  = (const float*)d_in[3];
    const float* W2  = (const float*)d_in[4];
    const float* b2  = (const float*)d_in[5];
    const float* W3  = (const float*)d_in[6];
    const float* b3  = (const float*)d_in[7];
    const float* W4  = (const float*)d_in[8];
    const float* b4  = (const float*)d_in[9];
    float* out = (float*)d_out;

    int B = in_sizes[0] / 3072;
    if (B > BMAX) B = BMAX;

    cudaFuncSetAttribute(som_kernel, cudaFuncAttributeMaxDynamicSharedMemorySize, 65536);
    cudaFuncSetAttribute(mlp_kernel, cudaFuncAttributeMaxDynamicSharedMemorySize, SM_U2 * 16);

    pack_som_kernel<<<1, 256>>>(som);
    prep_weights<<<256, 256>>>(W1, W2, W3, W4);
    int total_p = B * 225;
    som_kernel<<<(total_p + 255) / 256, 256, 65536>>>(x, B);
    mlp_kernel<<<(B + NIMG - 1) / NIMG, MTHREADS, SM_U2 * 16>>>(b1, b2, b3, b4, out, B);
}

// round 6
// speedup vs baseline: 1.8855x; 1.2624x over previous
#include <cuda_runtime.h>
#include <cstdint>

typedef unsigned long long ull;

#define BMAX 2048

// ---------------- device scratch ----------------
__device__ __align__(16) float g_pack[128 * 56];      // paired SOM codebook (+ -0.5*||s||^2)
__device__ __align__(16) float g_feat[BMAX * 450];    // SOM features [b][450]
// weights, layer-specific interleave [kg][j][og][4] (OPT=4 for L1, 2 for L2/L3)
__device__ __align__(16) float g_W1t[120 * 400 * 4];  // k padded 450->480
__device__ __align__(16) float g_W2t[100 * 200 * 4];
__device__ __align__(16) float g_W3t[50 * 100 * 4];
__device__ __align__(16) float g_W4t[25 * 10 * 4];    // [kg][o][4]

// ---------------- f32x2 helpers ----------------
__device__ __forceinline__ ull ffma2(ull a, ull b, ull c) {
    ull d;
    asm("fma.rn.f32x2 %0, %1, %2, %3;" : "=l"(d) : "l"(a), "l"(b), "l"(c));
    return d;
}
__device__ __forceinline__ ull pack2(float lo, float hi) {
    ull r;
    asm("mov.b64 %0, {%1, %2};" : "=l"(r) : "f"(lo), "f"(hi));
    return r;
}
__device__ __forceinline__ float lo32(ull v) { return __uint_as_float((unsigned)v); }
__device__ __forceinline__ float hi32(ull v) { return __uint_as_float((unsigned)(v >> 32)); }

__device__ __forceinline__ void cp_async16(uint32_t saddr, const float* g) {
    asm volatile("cp.async.cg.shared.global [%0], [%1], 16;" :: "r"(saddr), "l"(g));
}
#define CP_COMMIT() asm volatile("cp.async.commit_group;")
#define CP_WAIT0()  asm volatile("cp.async.wait_group 0;")

// ---------------- prep: pack SOM codebook ----------------
__global__ void pack_som_kernel(const float* __restrict__ som) {
    int c = threadIdx.x;
    if (c < 256) {
        int q = c >> 1, e = c & 1;
        float nrm = 0.f;
#pragma unroll
        for (int k = 0; k < 27; k++) {
            float v = som[c * 27 + k];
            nrm += v * v;
            g_pack[q * 56 + k * 2 + e] = v;
        }
        g_pack[q * 56 + 54 + e] = -0.5f * nrm;
    }
}

// ---------------- prep: interleave weights [kg][j][og][4] ----------------
__global__ void prep_weights(const float* __restrict__ W1, const float* __restrict__ W2,
                             const float* __restrict__ W3, const float* __restrict__ W4) {
    int i0 = blockIdx.x * blockDim.x + threadIdx.x;
    int stride = gridDim.x * blockDim.x;
    for (int i = i0; i < 120 * 400 * 4; i += stride) {
        int kr = i & 3, r = i >> 2;
        int og = r % 100; r /= 100;
        int j = r & 3; int kg = r >> 2;
        int k = kg * 4 + kr, o = og * 4 + j;
        g_W1t[i] = (k < 450) ? W1[o * 450 + k] : 0.f;
    }
    for (int i = i0; i < 100 * 200 * 4; i += stride) {
        int kr = i & 3, r = i >> 2;
        int og = r % 100; r /= 100;
        int j = r & 1; int kg = r >> 1;
        g_W2t[i] = W2[(og * 2 + j) * 400 + kg * 4 + kr];
    }
    for (int i = i0; i < 50 * 100 * 4; i += stride) {
        int kr = i & 3, r = i >> 2;
        int og = r % 50; r /= 50;
        int j = r & 1; int kg = r >> 1;
        g_W3t[i] = W3[(og * 2 + j) * 200 + kg * 4 + kr];
    }
    for (int i = i0; i < 25 * 10 * 4; i += stride) {
        int kg = i / 40, r = i % 40, o = r >> 2, kr = r & 3;
        g_W4t[i] = W4[o * 100 + kg * 4 + kr];
    }
}

// ---------------- SOM: 2 patches per thread, code LDS amortized 2x ----------------
// CTA covers 512 consecutive patches (thread owns p0+tid and p0+tid+256),
// spanning at most 4 images (48KB) + paired codebook (14.3KB) in smem.
// Inner iter (4 codes): 28 LDS.128 broadcast feeding 112 FFMA2 -> FMA-bound.
__global__ __launch_bounds__(256, 1) void som_kernel(const float* __restrict__ x, int B) {
    extern __shared__ float sm[];
    float* simg = sm;                          // 4 * 3072 floats
    double2* spk = (double2*)(sm + 12288);     // 128 * 14 double2

    int p0 = blockIdx.x * 512;
    int i0 = p0 / 225;
    int total = B * 225;
#pragma unroll
    for (int s = 0; s < 4; s++) {
        int img = i0 + s; if (img > B - 1) img = B - 1;
        const float4* xb = (const float4*)(x + (size_t)img * 3072);
        float4* d = (float4*)(simg + s * 3072);
        for (int i = threadIdx.x; i < 768; i += 256) d[i] = xb[i];
    }
    const double2* gp = (const double2*)g_pack;
    for (int i = threadIdx.x; i < 128 * 14; i += 256) spk[i] = gp[i];
    __syncthreads();

    int pA = p0 + threadIdx.x;
    int pB = pA + 256;
    bool wA = pA < total, wB = pB < total;
    if (!wA) pA = total - 1;
    if (!wB) pB = pA;

    int imgA = pA / 225, tA = pA - imgA * 225;
    int imgB = pB / 225, tB = pB - imgB * 225;
    const float* baseA = simg + (imgA - i0) * 3072 + (tA / 15) * 64 + (tA % 15) * 2;
    const float* baseB = simg + (imgB - i0) * 3072 + (tB / 15) * 64 + (tB % 15) * 2;

    ull pa[27], pb[27];
#pragma unroll
    for (int c = 0; c < 3; c++)
#pragma unroll
        for (int i = 0; i < 3; i++)
#pragma unroll
            for (int j = 0; j < 3; j++) {
                float vA = baseA[c * 1024 + i * 32 + j];
                float vB = baseB[c * 1024 + i * 32 + j];
                pa[c * 9 + i * 3 + j] = pack2(vA, vA);
                pb[c * 9 + i * 3 + j] = pack2(vB, vB);
            }

    float bestA = -3.4e38f, bestB = -3.4e38f;
    int idxA = 0, idxB = 0;
#pragma unroll 1
    for (int q = 0; q < 128; q += 2) {
        const double2* P0 = spk + q * 14;
        const double2* P1 = P0 + 14;
        double2 t0 = P0[13], t1 = P1[13];
        ull n0 = (ull)__double_as_longlong(t0.y);   // -0.5*||s||^2 pairs
        ull n1 = (ull)__double_as_longlong(t1.y);
        ull c26_0 = (ull)__double_as_longlong(t0.x);
        ull c26_1 = (ull)__double_as_longlong(t1.x);
        ull a0 = ffma2(pa[26], c26_0, n0);
        ull a1 = ffma2(pa[26], c26_1, n1);
        ull b0 = ffma2(pb[26], c26_0, n0);
        ull b1 = ffma2(pb[26], c26_1, n1);
#pragma unroll
        for (int j = 0; j < 13; j++) {
            double2 v0 = P0[j];
            double2 v1 = P1[j];
            ull w0 = (ull)__double_as_longlong(v0.x);
            ull w1 = (ull)__double_as_longlong(v0.y);
            ull w2 = (ull)__double_as_longlong(v1.x);
            ull w3 = (ull)__double_as_longlong(v1.y);
            a0 = ffma2(pa[2 * j],     w0, a0);
            b0 = ffma2(pb[2 * j],     w0, b0);
            a0 = ffma2(pa[2 * j + 1], w1, a0);
            b0 = ffma2(pb[2 * j + 1], w1, b0);
            a1 = ffma2(pa[2 * j],     w2, a1);
            b1 = ffma2(pb[2 * j],     w2, b1);
            a1 = ffma2(pa[2 * j + 1], w3, a1);
            b1 = ffma2(pb[2 * j + 1], w3, b1);
        }
        float sA0 = lo32(a0), sA1 = hi32(a0), sA2 = lo32(a1), sA3 = hi32(a1);
        if (sA0 > bestA) { bestA = sA0; idxA = 2 * q; }
        if (sA1 > bestA) { bestA = sA1; idxA = 2 * q + 1; }
        if (sA2 > bestA) { bestA = sA2; idxA = 2 * q + 2; }
        if (sA3 > bestA) { bestA = sA3; idxA = 2 * q + 3; }
        float sB0 = lo32(b0), sB1 = hi32(b0), sB2 = lo32(b1), sB3 = hi32(b1);
        if (sB0 > bestB) { bestB = sB0; idxB = 2 * q; }
        if (sB1 > bestB) { bestB = sB1; idxB = 2 * q + 1; }
        if (sB2 > bestB) { bestB = sB2; idxB = 2 * q + 2; }
        if (sB3 > bestB) { bestB = sB3; idxB = 2 * q + 3; }
    }
    if (wA) {
        float* fb = g_feat + (size_t)imgA * 450;
        fb[tA]       = (float)(idxA >> 4) * 0.0625f;
        fb[225 + tA] = (float)(idxA & 15) * 0.0625f;
    }
    if (wB) {
        float* fb = g_feat + (size_t)imgB * 450;
        fb[tB]       = (float)(idxB >> 4) * 0.0625f;
        fb[225 + tB] = (float)(idxB & 15) * 0.0625f;
    }
}

// ---------------- MLP: unchanged from R5 (passing, 66us) ----------------
#define MTHREADS 256
#define NIMG 8
#define WBUF_U2 2400

#define SA_U2 0
#define SB_U2 960
#define SW_U2 1760
#define SM_U2 (1760 + 2 * WBUF_U2)

template <int NGK, int CK, int NOUT, int OPT, int IMG, bool RELU>
__device__ __forceinline__ void layer(const float* __restrict__ Wg, const float* __restrict__ bias,
                                      const ulonglong2* sin, float* sout,
                                      ulonglong2* wbuf, uint32_t wbuf_s) {
    constexpr int NOG = NOUT / OPT;
    constexpr int NJG = NIMG / IMG;
    constexpr int JOBS = NOG * NJG;
    constexpr int CEF = CK * NOUT * 4;
    constexpr int NCH = NGK / CK;
    int tid = threadIdx.x;

    for (int i = tid; i < CEF / 4; i += MTHREADS) cp_async16(wbuf_s + i * 16, Wg + i * 4);
    CP_COMMIT(); CP_WAIT0();
    __syncthreads();

    int og = tid % NOG, jg = tid / NOG;
    bool active = tid < JOBS;
    ull acc[OPT * IMG];
#pragma unroll
    for (int i = 0; i < OPT * IMG; i++) acc[i] = 0;

#pragma unroll 1
    for (int c = 0; c < NCH; c++) {
        const ulonglong2* w = wbuf + (c & 1) * WBUF_U2;
        if (c + 1 < NCH) {
            uint32_t dst = wbuf_s + ((c + 1) & 1) * WBUF_U2 * 16;
            const float* src = Wg + (c + 1) * CEF;
            for (int i = tid; i < CEF / 4; i += MTHREADS) cp_async16(dst + i * 16, src + i * 4);
            CP_COMMIT();
        }
        if (active) {
#pragma unroll
            for (int kk = 0; kk < CK; kk++) {
                ulonglong2 av[IMG], wv[OPT];
#pragma unroll
                for (int i = 0; i < IMG; i++)
                    av[i] = sin[(c * CK + kk) * NIMG + jg * IMG + i];
#pragma unroll
                for (int j = 0; j < OPT; j++)
                    wv[j] = w[(kk * OPT + j) * NOG + og];
#pragma unroll
                for (int j = 0; j < OPT; j++)
#pragma unroll
                    for (int i = 0; i < IMG; i++) {
                        acc[j * IMG + i] = ffma2(av[i].x, wv[j].x, acc[j * IMG + i]);
                        acc[j * IMG + i] = ffma2(av[i].y, wv[j].y, acc[j * IMG + i]);
                    }
            }
        }
        CP_WAIT0();
        __syncthreads();
    }

    if (active) {
#pragma unroll
        for (int j = 0; j < OPT; j++) {
            int o = og * OPT + j;
            float bv = __ldg(bias + o);
#pragma unroll
            for (int i = 0; i < IMG; i++) {
                float v = lo32(acc[j * IMG + i]) + hi32(acc[j * IMG + i]) + bv;
                if (RELU) v = fmaxf(v, 0.f);
                int im = jg * IMG + i;
                sout[((o >> 2) * NIMG + im) * 4 + (o & 3)] = v;
            }
        }
    }
    __syncthreads();
}

__global__ __launch_bounds__(MTHREADS, 2) void mlp_kernel(const float* __restrict__ b1, const float* __restrict__ b2,
                                                          const float* __restrict__ b3, const float* __restrict__ b4,
                                                          float* __restrict__ out, int B) {
    extern __shared__ ulonglong2 smu[];
    ulonglong2* A = smu + SA_U2;
    ulonglong2* Bm = smu + SB_U2;
    ulonglong2* wbuf = smu + SW_U2;
    uint32_t wbuf_s = (uint32_t)__cvta_generic_to_shared(wbuf);
    int tid = threadIdx.x;
    int b0 = blockIdx.x * NIMG;

    float* Af = (float*)A;
    for (int i = tid; i < 120 * NIMG * 4; i += MTHREADS) {
        int kg = i >> 5, r = i & 31, im = r >> 2, kr = r & 3;
        int k = kg * 4 + kr;
        int b = b0 + im; if (b > B - 1) b = B - 1;
        Af[i] = (k < 450) ? g_feat[(size_t)b * 450 + k] : 0.f;
    }
    __syncthreads();

    layer<120, 6, 400, 4, 4, true>(g_W1t, b1, A, (float*)Bm, wbuf, wbuf_s);
    layer<100, 10, 200, 2, 4, true>(g_W2t, b2, Bm, (float*)A, wbuf, wbuf_s);
    layer<50, 10, 100, 2, 2, true>(g_W3t, b3, A, (float*)Bm, wbuf, wbuf_s);

    for (int job = tid; job < 10 * NIMG; job += MTHREADS) {
        int o = job % 10, im = job / 10;
        const ulonglong2* ar = Bm + im;
        ull acc = 0;
#pragma unroll
        for (int kg = 0; kg < 25; kg++) {
            ulonglong2 wv = __ldg((const ulonglong2*)g_W4t + kg * 10 + o);
            ulonglong2 av = ar[kg * NIMG];
            acc = ffma2(av.x, wv.x, acc);
            acc = ffma2(av.y, wv.y, acc);
        }
        int b = b0 + im;
        if (b < B) out[(size_t)b * 10 + o] = lo32(acc) + hi32(acc) + __ldg(b4 + o);
    }
}

// ---------------- launch ----------------
extern "C" void kernel_launch(void* const* d_in, const int* in_sizes, int n_in,
                              void* d_out, int out_size) {
    const float* x   = (const float*)d_in[0];
    const float* som = (const float*)d_in[1];
    const float* W1  = (const float*)d_in[2];
    const float* b1  = (const float*)d_in[3];
    const float* W2  = (const float*)d_in[4];
    const float* b2  = (const float*)d_in[5];
    const float* W3  = (const float*)d_in[6];
    const float* b3  = (const float*)d_in[7];
    const float* W4  = (const float*)d_in[8];
    const float* b4  = (const float*)d_in[9];
    float* out = (float*)d_out;

    int B = in_sizes[0] / 3072;
    if (B > BMAX) B = BMAX;

    int som_smem = (4 * 3072) * 4 + 128 * 14 * 16;   // 49152 + 28672 = 63.9KB... (floats + double2)
    cudaFuncSetAttribute(som_kernel, cudaFuncAttributeMaxDynamicSharedMemorySize, som_smem);
    cudaFuncSetAttribute(mlp_kernel, cudaFuncAttributeMaxDynamicSharedMemorySize, SM_U2 * 16);

    pack_som_kernel<<<1, 256>>>(som);
    prep_weights<<<256, 256>>>(W1, W2, W3, W4);
    int total_p = B * 225;
    som_kernel<<<(total_p + 511) / 512, 256, som_smem>>>(x, B);
    mlp_kernel<<<(B + NIMG - 1) / NIMG, MTHREADS, SM_U2 * 16>>>(b1, b2, b3, b4, out, B);
}

// round 7
// speedup vs baseline: 1.9655x; 1.0424x over previous
#include <cuda_runtime.h>
#include <cstdint>

typedef unsigned long long ull;

#define BMAX 2048

// ---------------- device scratch ----------------
__device__ __align__(16) float g_pack[128 * 56];      // paired SOM codebook (+ -0.5*||s||^2)
__device__ __align__(16) float g_feat[BMAX * 450];    // SOM features [b][450]
// weights interleaved [kg][j][og][4] per-layer (OPT: 4/2/2)
__device__ __align__(16) float g_W1t[120 * 4 * 100 * 4];  // k padded 450->480
__device__ __align__(16) float g_W2t[100 * 2 * 100 * 4];
__device__ __align__(16) float g_W3t[50 * 2 * 50 * 4];
__device__ __align__(16) float g_W4t[25 * 10 * 4];        // [kg][o][4]

// ---------------- f32x2 helpers ----------------
__device__ __forceinline__ ull ffma2(ull a, ull b, ull c) {
    ull d;
    asm("fma.rn.f32x2 %0, %1, %2, %3;" : "=l"(d) : "l"(a), "l"(b), "l"(c));
    return d;
}
__device__ __forceinline__ ull pack2(float lo, float hi) {
    ull r;
    asm("mov.b64 %0, {%1, %2};" : "=l"(r) : "f"(lo), "f"(hi));
    return r;
}
__device__ __forceinline__ float lo32(ull v) { return __uint_as_float((unsigned)v); }
__device__ __forceinline__ float hi32(ull v) { return __uint_as_float((unsigned)(v >> 32)); }

__device__ __forceinline__ void cp_async16(uint32_t saddr, const float* g) {
    asm volatile("cp.async.cg.shared.global [%0], [%1], 16;" :: "r"(saddr), "l"(g));
}
#define CP_COMMIT() asm volatile("cp.async.commit_group;")
#define CP_WAIT0()  asm volatile("cp.async.wait_group 0;")

// ---------------- prep: SOM pack (block 0) + weight interleave ----------------
__global__ void prep_kernel(const float* __restrict__ som,
                            const float* __restrict__ W1, const float* __restrict__ W2,
                            const float* __restrict__ W3, const float* __restrict__ W4) {
    if (blockIdx.x == 0) {
        int c = threadIdx.x;
        if (c < 256) {
            int q = c >> 1, e = c & 1;
            float nrm = 0.f;
#pragma unroll
            for (int k = 0; k < 27; k++) {
                float v = som[c * 27 + k];
                nrm += v * v;
                g_pack[q * 56 + k * 2 + e] = v;
            }
            g_pack[q * 56 + 54 + e] = -0.5f * nrm;
        }
    }
    int i0 = blockIdx.x * blockDim.x + threadIdx.x;
    int stride = gridDim.x * blockDim.x;
    // L1: [kg(120)][j(4)][og(100)][kr(4)]
    for (int i = i0; i < 120 * 4 * 100 * 4; i += stride) {
        int kr = i & 3, r = i >> 2;
        int og = r % 100; r /= 100;
        int j = r & 3; int kg = r >> 2;
        int k = kg * 4 + kr, o = og * 4 + j;
        g_W1t[i] = (k < 450) ? W1[o * 450 + k] : 0.f;
    }
    // L2: [kg(100)][j(2)][og(100)][kr]
    for (int i = i0; i < 100 * 2 * 100 * 4; i += stride) {
        int kr = i & 3, r = i >> 2;
        int og = r % 100; r /= 100;
        int j = r & 1; int kg = r >> 1;
        g_W2t[i] = W2[(og * 2 + j) * 400 + kg * 4 + kr];
    }
    // L3: [kg(50)][j(2)][og(50)][kr]
    for (int i = i0; i < 50 * 2 * 50 * 4; i += stride) {
        int kr = i & 3, r = i >> 2;
        int og = r % 50; r /= 50;
        int j = r & 1; int kg = r >> 1;
        g_W3t[i] = W3[(og * 2 + j) * 200 + kg * 4 + kr];
    }
    // L4: [kg][o][4]
    for (int i = i0; i < 25 * 10 * 4; i += stride) {
        int kg = i / 40, r = i % 40, o = r >> 2, kr = r & 3;
        g_W4t[i] = W4[o * 100 + kg * 4 + kr];
    }
}

// ---------------- SOM (unchanged from R6, passing ~125us) ----------------
__global__ __launch_bounds__(256, 1) void som_kernel(const float* __restrict__ x, int B) {
    extern __shared__ float sm[];
    float* simg = sm;                          // 4 * 3072 floats
    double2* spk = (double2*)(sm + 12288);     // 128 * 14 double2

    int p0 = blockIdx.x * 512;
    int i0 = p0 / 225;
    int total = B * 225;
#pragma unroll
    for (int s = 0; s < 4; s++) {
        int img = i0 + s; if (img > B - 1) img = B - 1;
        const float4* xb = (const float4*)(x + (size_t)img * 3072);
        float4* d = (float4*)(simg + s * 3072);
        for (int i = threadIdx.x; i < 768; i += 256) d[i] = xb[i];
    }
    const double2* gp = (const double2*)g_pack;
    for (int i = threadIdx.x; i < 128 * 14; i += 256) spk[i] = gp[i];
    __syncthreads();

    int pA = p0 + threadIdx.x;
    int pB = pA + 256;
    bool wA = pA < total, wB = pB < total;
    if (!wA) pA = total - 1;
    if (!wB) pB = pA;

    int imgA = pA / 225, tA = pA - imgA * 225;
    int imgB = pB / 225, tB = pB - imgB * 225;
    const float* baseA = simg + (imgA - i0) * 3072 + (tA / 15) * 64 + (tA % 15) * 2;
    const float* baseB = simg + (imgB - i0) * 3072 + (tB / 15) * 64 + (tB % 15) * 2;

    ull pa[27], pb[27];
#pragma unroll
    for (int c = 0; c < 3; c++)
#pragma unroll
        for (int i = 0; i < 3; i++)
#pragma unroll
            for (int j = 0; j < 3; j++) {
                float vA = baseA[c * 1024 + i * 32 + j];
                float vB = baseB[c * 1024 + i * 32 + j];
                pa[c * 9 + i * 3 + j] = pack2(vA, vA);
                pb[c * 9 + i * 3 + j] = pack2(vB, vB);
            }

    float bestA = -3.4e38f, bestB = -3.4e38f;
    int idxA = 0, idxB = 0;
#pragma unroll 1
    for (int q = 0; q < 128; q += 2) {
        const double2* P0 = spk + q * 14;
        const double2* P1 = P0 + 14;
        double2 t0 = P0[13], t1 = P1[13];
        ull n0 = (ull)__double_as_longlong(t0.y);
        ull n1 = (ull)__double_as_longlong(t1.y);
        ull c26_0 = (ull)__double_as_longlong(t0.x);
        ull c26_1 = (ull)__double_as_longlong(t1.x);
        ull a0 = ffma2(pa[26], c26_0, n0);
        ull a1 = ffma2(pa[26], c26_1, n1);
        ull b0 = ffma2(pb[26], c26_0, n0);
        ull b1 = ffma2(pb[26], c26_1, n1);
#pragma unroll
        for (int j = 0; j < 13; j++) {
            double2 v0 = P0[j];
            double2 v1 = P1[j];
            ull w0 = (ull)__double_as_longlong(v0.x);
            ull w1 = (ull)__double_as_longlong(v0.y);
            ull w2 = (ull)__double_as_longlong(v1.x);
            ull w3 = (ull)__double_as_longlong(v1.y);
            a0 = ffma2(pa[2 * j],     w0, a0);
            b0 = ffma2(pb[2 * j],     w0, b0);
            a0 = ffma2(pa[2 * j + 1], w1, a0);
            b0 = ffma2(pb[2 * j + 1], w1, b0);
            a1 = ffma2(pa[2 * j],     w2, a1);
            b1 = ffma2(pb[2 * j],     w2, b1);
            a1 = ffma2(pa[2 * j + 1], w3, a1);
            b1 = ffma2(pb[2 * j + 1], w3, b1);
        }
        float sA0 = lo32(a0), sA1 = hi32(a0), sA2 = lo32(a1), sA3 = hi32(a1);
        if (sA0 > bestA) { bestA = sA0; idxA = 2 * q; }
        if (sA1 > bestA) { bestA = sA1; idxA = 2 * q + 1; }
        if (sA2 > bestA) { bestA = sA2; idxA = 2 * q + 2; }
        if (sA3 > bestA) { bestA = sA3; idxA = 2 * q + 3; }
        float sB0 = lo32(b0), sB1 = hi32(b0), sB2 = lo32(b1), sB3 = hi32(b1);
        if (sB0 > bestB) { bestB = sB0; idxB = 2 * q; }
        if (sB1 > bestB) { bestB = sB1; idxB = 2 * q + 1; }
        if (sB2 > bestB) { bestB = sB2; idxB = 2 * q + 2; }
        if (sB3 > bestB) { bestB = sB3; idxB = 2 * q + 3; }
    }
    if (wA) {
        float* fb = g_feat + (size_t)imgA * 450;
        fb[tA]       = (float)(idxA >> 4) * 0.0625f;
        fb[225 + tA] = (float)(idxA & 15) * 0.0625f;
    }
    if (wB) {
        float* fb = g_feat + (size_t)imgB * 450;
        fb[tB]       = (float)(idxB >> 4) * 0.0625f;
        fb[225 + tB] = (float)(idxB & 15) * 0.0625f;
    }
}

// ---------------- MLP: 16 imgs/CTA, grid 128, OPTxIMG=4x8 / 2x8 / 2x4 ----------------
// Act smem [kg][img(16)] ulonglong2; weights smem [kg][j][og] ulonglong2,
// double-buffered cp.async. Job: jg = tid/NOGP (warp-uniform), og = tid%NOGP.
#define MTHREADS 256
#define NIMG 16
#define WBUF_U2 3200                // L1 chunk: 8 kg x 400 outs = 3200 u2 (51.2KB)

#define SA_U2 0                     // 120*16 = 1920 u2
#define SB_U2 1920                  // 100*16 = 1600 u2
#define SW_U2 3520
#define SM_U2 (3520 + 2 * WBUF_U2)  // 9920 u2 = 158.7KB

template <int NGK, int CK, int OPT, int NOG, int NOGP, int IMG, bool RELU>
__device__ __forceinline__ void layer(const float* __restrict__ Wg, const float* __restrict__ bias,
                                      const ulonglong2* sin, float* sout,
                                      ulonglong2* wbuf, uint32_t wbuf_s) {
    constexpr int CEF = CK * OPT * NOG * 4;   // floats per chunk
    constexpr int NCH = NGK / CK;             // exact
    int tid = threadIdx.x;

    // stage chunk 0
    for (int i = tid; i < CEF / 4; i += MTHREADS) cp_async16(wbuf_s + i * 16, Wg + i * 4);
    CP_COMMIT(); CP_WAIT0();
    __syncthreads();

    int og = tid % NOGP, jg = tid / NOGP;
    bool active = og < NOG;
    ull acc[OPT * IMG];
#pragma unroll
    for (int i = 0; i < OPT * IMG; i++) acc[i] = 0;

#pragma unroll 1
    for (int c = 0; c < NCH; c++) {
        const ulonglong2* w = wbuf + (c & 1) * WBUF_U2;
        if (c + 1 < NCH) {
            uint32_t dst = wbuf_s + ((c + 1) & 1) * WBUF_U2 * 16;
            const float* src = Wg + (c + 1) * CEF;
            for (int i = tid; i < CEF / 4; i += MTHREADS) cp_async16(dst + i * 16, src + i * 4);
            CP_COMMIT();
        }
        if (active) {
#pragma unroll
            for (int kk = 0; kk < CK; kk++) {
                ulonglong2 av[IMG], wv[OPT];
#pragma unroll
                for (int i = 0; i < IMG; i++)
                    av[i] = sin[(c * CK + kk) * NIMG + jg * IMG + i];
#pragma unroll
                for (int j = 0; j < OPT; j++)
                    wv[j] = w[(kk * OPT + j) * NOG + og];
#pragma unroll
                for (int j = 0; j < OPT; j++)
#pragma unroll
                    for (int i = 0; i < IMG; i++) {
                        acc[j * IMG + i] = ffma2(av[i].x, wv[j].x, acc[j * IMG + i]);
                        acc[j * IMG + i] = ffma2(av[i].y, wv[j].y, acc[j * IMG + i]);
                    }
            }
        }
        CP_WAIT0();
        __syncthreads();
    }

    if (active) {
#pragma unroll
        for (int j = 0; j < OPT; j++) {
            int o = og * OPT + j;
            float bv = __ldg(bias + o);
#pragma unroll
            for (int i = 0; i < IMG; i++) {
                float v = lo32(acc[j * IMG + i]) + hi32(acc[j * IMG + i]) + bv;
                if (RELU) v = fmaxf(v, 0.f);
                int im = jg * IMG + i;
                sout[((o >> 2) * NIMG + im) * 4 + (o & 3)] = v;
            }
        }
    }
    __syncthreads();
}

__global__ __launch_bounds__(MTHREADS, 1) void mlp_kernel(const float* __restrict__ b1, const float* __restrict__ b2,
                                                          const float* __restrict__ b3, const float* __restrict__ b4,
                                                          float* __restrict__ out, int B) {
    extern __shared__ ulonglong2 smu[];
    ulonglong2* A = smu + SA_U2;
    ulonglong2* Bm = smu + SB_U2;
    ulonglong2* wbuf = smu + SW_U2;
    uint32_t wbuf_s = (uint32_t)__cvta_generic_to_shared(wbuf);
    int tid = threadIdx.x;
    int b0 = blockIdx.x * NIMG;

    // features -> A [kg][img(16)][4], zero-pad k >= 450
    float* Af = (float*)A;
    for (int i = tid; i < 120 * NIMG * 4; i += MTHREADS) {
        int kg = i >> 6, r = i & 63, im = r >> 2, kr = r & 3;
        int k = kg * 4 + kr;
        int b = b0 + im; if (b > B - 1) b = B - 1;
        Af[i] = (k < 450) ? g_feat[(size_t)b * 450 + k] : 0.f;
    }
    __syncthreads();

    layer<120, 8, 4, 100, 128, 8, true>(g_W1t, b1, A, (float*)Bm, wbuf, wbuf_s);   // 450->400
    layer<100, 10, 2, 100, 128, 8, true>(g_W2t, b2, Bm, (float*)A, wbuf, wbuf_s);  // 400->200
    layer<50, 10, 2, 50, 64, 4, true>(g_W3t, b3, A, (float*)Bm, wbuf, wbuf_s);     // 200->100

    // final 100 -> 10 (L1-resident __ldg weights)
    for (int job = tid; job < 10 * NIMG; job += MTHREADS) {
        int o = job % 10, im = job / 10;
        const ulonglong2* ar = Bm + im;
        ull acc = 0;
#pragma unroll
        for (int kg = 0; kg < 25; kg++) {
            ulonglong2 wv = __ldg((const ulonglong2*)g_W4t + kg * 10 + o);
            ulonglong2 av = ar[kg * NIMG];
            acc = ffma2(av.x, wv.x, acc);
            acc = ffma2(av.y, wv.y, acc);
        }
        int b = b0 + im;
        if (b < B) out[(size_t)b * 10 + o] = lo32(acc) + hi32(acc) + __ldg(b4 + o);
    }
}

// ---------------- launch ----------------
extern "C" void kernel_launch(void* const* d_in, const int* in_sizes, int n_in,
                              void* d_out, int out_size) {
    const float* x   = (const float*)d_in[0];
    const float* som = (const float*)d_in[1];
    const float* W1  = (const float*)d_in[2];
    const float* b1  = (const float*)d_in[3];
    const float* W2  = (const float*)d_in[4];
    const float* b2  = (const float*)d_in[5];
    const float* W3  = (const float*)d_in[6];
    const float* b3  = (const float*)d_in[7];
    const float* W4  = (const float*)d_in[8];
    const float* b4  = (const float*)d_in[9];
    float* out = (float*)d_out;

    int B = in_sizes[0] / 3072;
    if (B > BMAX) B = BMAX;

    int som_smem = (4 * 3072) * 4 + 128 * 14 * 16;
    cudaFuncSetAttribute(som_kernel, cudaFuncAttributeMaxDynamicSharedMemorySize, som_smem);
    cudaFuncSetAttribute(mlp_kernel, cudaFuncAttributeMaxDynamicSharedMemorySize, SM_U2 * 16);

    prep_kernel<<<256, 256>>>(som, W1, W2, W3, W4);
    int total_p = B * 225;
    som_kernel<<<(total_p + 511) / 512, 256, som_smem>>>(x, B);
    mlp_kernel<<<(B + NIMG - 1) / NIMG, MTHREADS, SM_U2 * 16>>>(b1, b2, b3, b4, out, B);
}